// round 7
// baseline (speedup 1.0000x reference)
#include <cuda_runtime.h>

#define NLAYERS 7
#define EPS_F 1e-5f

// Shapes (fixed by setup_inputs): bsz=8, C=8, QL=KL=128, A=8, cross_range=2
// pw / out: [64, 1024, 1024] f32;  conv_w: [7,8,8,1,3]; conv_b: [7,8]; prelu_a: [7]
//
// Warp-specialized CTA, one CTA per (b, q):
//   warps 4-7: pure zero streamers (248/256 float4-columns incl. self block),
//              no barriers, start at cycle 0, exit when done.
//   warps 0-3: 7-layer residual conv stack (each thread: 1 slab x 2 channels),
//              synced by named barrier bar.sync 1,128; write the 8 band
//              float4-columns at the end. Address sets are disjoint.

__device__ __forceinline__ void stcs4(float* p, float4 v) {
    asm volatile("st.global.cs.v4.f32 [%0], {%1,%2,%3,%4};"
                 :: "l"(p), "f"(v.x), "f"(v.y), "f"(v.z), "f"(v.w) : "memory");
}
__device__ __forceinline__ void convbar() {
    asm volatile("bar.sync 1, 128;" ::: "memory");
}

__global__ __launch_bounds__(256, 4)
void sag_ws(const float* __restrict__ pw,
            const float* __restrict__ conv_w,
            const float* __restrict__ conv_b,
            const float* __restrict__ prelu_a,
            float* __restrict__ out)
{
    __shared__ float4 sW4[NLAYERS][8][8];            // [l][ci][co] = (k0,k1,k2,_)
    __shared__ float  sB [NLAYERS][8];
    __shared__ float  sA [NLAYERS];
    __shared__ __align__(16) float sD0[32 * 68];     // ping  [slab]*68 + [ci]*8 + w
    __shared__ __align__(16) float sD1[32 * 68];     // pong
    __shared__ __align__(16) float sRes[4][8][8][8]; // x, later we  [pp][hh][co][w]
    __shared__ float  sPS[4][8][8];                  // partial row sums
    __shared__ float  sInv[8][8];                    // 1/(rowsum+eps) [hh][co]

    const int tid = threadIdx.x;
    const int b = blockIdx.x >> 7;            // batch
    const int i = blockIdx.x & 127;           // query index
    const size_t base = ((size_t)(b * 8) * 1024 + (size_t)i * 8) * 1024;

    // ================= STORE WARPS (tid 128..255) =================
    if (tid >= 128) {
        const int t = tid - 128;
        const float4 z = make_float4(0.f, 0.f, 0.f, 0.f);
        #pragma unroll
        for (int g = 0; g < 2; g++) {
            const int c  = t + g * 128;       // float4-column 0..255
            const int dd = (c >> 1) - i;      // block-col offset from i
            if (dd == 0 || dd < -2 || dd > 2) {   // not a live band column
                float* col = out + base + (size_t)c * 4;
                #pragma unroll 2
                for (int rc = 0; rc < 8; rc++) {
                    float* pr = col + (size_t)rc * (1024 * 1024);
                    #pragma unroll
                    for (int rh = 0; rh < 8; rh++)
                        stcs4(pr + rh * 1024, z);
                }
            }
        }
        return;
    }

    // ================= CONV WARPS (tid 0..127) =================
    // thread = (slab, co-pair): slab = tid>>2 (32 slabs), co2 = (tid&3)*2
    const int slab = tid >> 2;
    const int co2  = (tid & 3) << 1;
    const int pp   = slab >> 3;
    const int hh   = slab & 7;
    const int doff = (pp < 2) ? (pp - 2) : (pp - 1);  // {-2,-1,1,2}
    const int j    = i + doff;
    const bool pvalid = (j >= 0) && (j < 128);

    // conv params -> SMEM
    for (int t = tid; t < NLAYERS * 64; t += 128) {
        const int l = t >> 6, rem = t & 63, wco = rem >> 3, wci = rem & 7;
        const float* src = conv_w + ((l * 8 + wco) * 8 + wci) * 3;
        sW4[l][wci][wco] = make_float4(src[0], src[1], src[2], 0.f);
    }
    if (tid < NLAYERS * 8) (&sB[0][0])[tid] = conv_b[tid];
    if (tid < NLAYERS)     sA[tid] = prelu_a[tid];

    // load x for both channels (8 contiguous floats each)
    float4 a0 = make_float4(0.f,0.f,0.f,0.f), a1 = a0, b0 = a0, b1 = a0;
    if (pvalid) {
        const float* srcA = pw +
            ((size_t)((b * 8 + co2) * 1024 + (i * 8 + hh)) * 1024 + (size_t)j * 8);
        const float* srcB = srcA + (size_t)1024 * 1024;   // co2+1
        a0 = *(const float4*)srcA; a1 = *(const float4*)(srcA + 4);
        b0 = *(const float4*)srcB; b1 = *(const float4*)(srcB + 4);
    }
    {
        float* rowA = sD0 + slab * 68 + co2 * 8;
        *(float4*)rowA        = a0;  *(float4*)(rowA + 4)  = a1;
        *(float4*)(rowA + 8)  = b0;  *(float4*)(rowA + 12) = b1;
        *(float4*)&sRes[pp][hh][co2][0]     = a0;
        *(float4*)&sRes[pp][hh][co2][4]     = a1;
        *(float4*)&sRes[pp][hh][co2 + 1][0] = b0;
        *(float4*)&sRes[pp][hh][co2 + 1][4] = b1;
    }
    convbar();

    // ---- 7-layer residual conv stack ----
    float* cur = sD0;
    float* nxt = sD1;
    #pragma unroll 1
    for (int l = 0; l < NLAYERS; l++) {
        float accA[8], accB[8];
        const float biasA = sB[l][co2];
        const float biasB = sB[l][co2 + 1];
        #pragma unroll
        for (int w = 0; w < 8; w++) { accA[w] = biasA; accB[w] = biasB; }

        #pragma unroll
        for (int ci = 0; ci < 8; ci++) {
            const float4 wa = sW4[l][ci][co2];
            const float4 wb = sW4[l][ci][co2 + 1];
            const float* inr = cur + slab * 68 + ci * 8;
            const float4 ra = *(const float4*)inr;
            const float4 rb = *(const float4*)(inr + 4);
            accA[0] += wa.y * ra.x + wa.z * ra.y;
            accA[1] += wa.x * ra.x + wa.y * ra.y + wa.z * ra.z;
            accA[2] += wa.x * ra.y + wa.y * ra.z + wa.z * ra.w;
            accA[3] += wa.x * ra.z + wa.y * ra.w + wa.z * rb.x;
            accA[4] += wa.x * ra.w + wa.y * rb.x + wa.z * rb.y;
            accA[5] += wa.x * rb.x + wa.y * rb.y + wa.z * rb.z;
            accA[6] += wa.x * rb.y + wa.y * rb.z + wa.z * rb.w;
            accA[7] += wa.x * rb.z + wa.y * rb.w;
            accB[0] += wb.y * ra.x + wb.z * ra.y;
            accB[1] += wb.x * ra.x + wb.y * ra.y + wb.z * ra.z;
            accB[2] += wb.x * ra.y + wb.y * ra.z + wb.z * ra.w;
            accB[3] += wb.x * ra.z + wb.y * ra.w + wb.z * rb.x;
            accB[4] += wb.x * ra.w + wb.y * rb.x + wb.z * rb.y;
            accB[5] += wb.x * rb.x + wb.y * rb.y + wb.z * rb.z;
            accB[6] += wb.x * rb.y + wb.y * rb.z + wb.z * rb.w;
            accB[7] += wb.x * rb.z + wb.y * rb.w;
        }

        const float pa = sA[l];
        const float* selfA = cur + slab * 68 + co2 * 8;
        const float4 sa0 = *(const float4*)selfA;
        const float4 sa1 = *(const float4*)(selfA + 4);
        const float4 sb0 = *(const float4*)(selfA + 8);
        const float4 sb1 = *(const float4*)(selfA + 12);
        float4 oA0, oA1, oB0, oB1;
        oA0.x = ((accA[0]>=0.f)?accA[0]:pa*accA[0]) + sa0.x;
        oA0.y = ((accA[1]>=0.f)?accA[1]:pa*accA[1]) + sa0.y;
        oA0.z = ((accA[2]>=0.f)?accA[2]:pa*accA[2]) + sa0.z;
        oA0.w = ((accA[3]>=0.f)?accA[3]:pa*accA[3]) + sa0.w;
        oA1.x = ((accA[4]>=0.f)?accA[4]:pa*accA[4]) + sa1.x;
        oA1.y = ((accA[5]>=0.f)?accA[5]:pa*accA[5]) + sa1.y;
        oA1.z = ((accA[6]>=0.f)?accA[6]:pa*accA[6]) + sa1.z;
        oA1.w = ((accA[7]>=0.f)?accA[7]:pa*accA[7]) + sa1.w;
        oB0.x = ((accB[0]>=0.f)?accB[0]:pa*accB[0]) + sb0.x;
        oB0.y = ((accB[1]>=0.f)?accB[1]:pa*accB[1]) + sb0.y;
        oB0.z = ((accB[2]>=0.f)?accB[2]:pa*accB[2]) + sb0.z;
        oB0.w = ((accB[3]>=0.f)?accB[3]:pa*accB[3]) + sb0.w;
        oB1.x = ((accB[4]>=0.f)?accB[4]:pa*accB[4]) + sb1.x;
        oB1.y = ((accB[5]>=0.f)?accB[5]:pa*accB[5]) + sb1.y;
        oB1.z = ((accB[6]>=0.f)?accB[6]:pa*accB[6]) + sb1.z;
        oB1.w = ((accB[7]>=0.f)?accB[7]:pa*accB[7]) + sb1.w;
        float* outr = nxt + slab * 68 + co2 * 8;
        *(float4*)outr        = oA0;  *(float4*)(outr + 4)  = oA1;
        *(float4*)(outr + 8)  = oB0;  *(float4*)(outr + 12) = oB1;
        convbar();
        float* tmp = cur; cur = nxt; nxt = tmp;
    }

    // ---- we = expm1(relu(x - sigmoid(conv)) * (1-eye)) for both channels ----
    #pragma unroll
    for (int cc = 0; cc < 2; cc++) {
        const int co = co2 + cc;
        const float* cr = cur + slab * 68 + co * 8;
        const float4 c0 = *(const float4*)cr;
        const float4 c1 = *(const float4*)(cr + 4);
        const float4 x0 = *(const float4*)&sRes[pp][hh][co][0];
        const float4 x1 = *(const float4*)&sRes[pp][hh][co][4];
        float cv[8] = {c0.x,c0.y,c0.z,c0.w,c1.x,c1.y,c1.z,c1.w};
        float xv[8] = {x0.x,x0.y,x0.z,x0.w,x1.x,x1.y,x1.z,x1.w};
        float we[8];
        float partial = 0.f;
        #pragma unroll
        for (int w = 0; w < 8; w++) {
            const float sg = 1.f / (1.f + __expf(-cv[w]));
            float sp = fmaxf(xv[w] - sg, 0.f);
            if (hh == w) sp = 0.f;
            float v = expm1f(sp);
            if (!pvalid) v = 0.f;
            we[w] = v;
            partial += v;
        }
        *(float4*)&sRes[pp][hh][co][0] = make_float4(we[0],we[1],we[2],we[3]);
        *(float4*)&sRes[pp][hh][co][4] = make_float4(we[4],we[5],we[6],we[7]);
        sPS[pp][hh][co] = partial;
    }
    convbar();

    if (tid < 64) {
        const int th = tid >> 3, tc = tid & 7;
        const float s = sPS[0][th][tc] + sPS[1][th][tc] + sPS[2][th][tc] + sPS[3][th][tc];
        sInv[th][tc] = 1.f / (s + EPS_F);
    }
    convbar();

    // ---- band stores: 8 float4-columns x 64 rows over 128 threads ----
    {
        const int cI   = tid >> 4;          // 0..7 band column slot
        const int r0   = tid & 15;          // row group start
        const int dIdx = cI >> 1;           // pp index
        const int half = cI & 1;
        const int dv   = (dIdx < 2) ? (dIdx - 2) : (dIdx - 1);
        const int jb   = i + dv;
        if (jb >= 0 && jb < 128) {
            const int fc = 2 * jb + half;
            const int w0 = half * 4;
            #pragma unroll
            for (int g = 0; g < 4; g++) {
                const int rr = r0 + g * 16;     // 0..63
                const int rc = rr >> 3, rh = rr & 7;
                const float4 rv = *(const float4*)&sRes[dIdx][rh][rc][w0];
                const float inv = sInv[rh][rc];
                stcs4(out + base + (size_t)rc * (1024*1024) + rh * 1024 + fc * 4,
                      make_float4(rv.x*inv, rv.y*inv, rv.z*inv, rv.w*inv));
            }
        }
    }
}

extern "C" void kernel_launch(void* const* d_in, const int* in_sizes, int n_in,
                              void* d_out, int out_size) {
    const float* pw = (const float*)d_in[0];
    const float* cw = (const float*)d_in[1];
    const float* cb = (const float*)d_in[2];
    const float* pa = (const float*)d_in[3];
    sag_ws<<<1024, 256>>>(pw, cw, cb, pa, (float*)d_out);
}

// round 8
// speedup vs baseline: 1.0070x; 1.0070x over previous
#include <cuda_runtime.h>

#define NLAYERS 7
#define EPS_F 1e-5f

// Shapes (fixed by setup_inputs): bsz=8, C=8, QL=KL=128, A=8, cross_range=2
// pw / out: [64, 1024, 1024] f32;  conv_w: [7,8,8,1,3]; conv_b: [7,8]; prelu_a: [7]
//
// Warp-specialized CTA, one CTA per (b, q):
//   warps 4-7: pure zero streamers (248/256 float4-columns incl. self block),
//              no barriers, start at cycle 0, exit when done.
//   warps 0-3: 7-layer residual conv stack (each thread: 1 slab x 2 channels),
//              synced by named barrier bar.sync 1,128; write the 8 band
//              float4-columns at the end. Address sets are disjoint.

__device__ __forceinline__ void stcs4(float* p, float4 v) {
    asm volatile("st.global.cs.v4.f32 [%0], {%1,%2,%3,%4};"
                 :: "l"(p), "f"(v.x), "f"(v.y), "f"(v.z), "f"(v.w) : "memory");
}
__device__ __forceinline__ void convbar() {
    asm volatile("bar.sync 1, 128;" ::: "memory");
}

__global__ __launch_bounds__(256, 4)
void sag_ws(const float* __restrict__ pw,
            const float* __restrict__ conv_w,
            const float* __restrict__ conv_b,
            const float* __restrict__ prelu_a,
            float* __restrict__ out)
{
    __shared__ float4 sW4[NLAYERS][8][8];            // [l][ci][co] = (k0,k1,k2,_)
    __shared__ float  sB [NLAYERS][8];
    __shared__ float  sA [NLAYERS];
    __shared__ __align__(16) float sD0[32 * 68];     // ping  [slab]*68 + [ci]*8 + w
    __shared__ __align__(16) float sD1[32 * 68];     // pong
    __shared__ __align__(16) float sRes[4][8][8][8]; // x, later we  [pp][hh][co][w]
    __shared__ float  sPS[4][8][8];                  // partial row sums
    __shared__ float  sInv[8][8];                    // 1/(rowsum+eps) [hh][co]

    const int tid = threadIdx.x;
    const int b = blockIdx.x >> 7;            // batch
    const int i = blockIdx.x & 127;           // query index
    const size_t base = ((size_t)(b * 8) * 1024 + (size_t)i * 8) * 1024;

    // ================= STORE WARPS (tid 128..255) =================
    if (tid >= 128) {
        const int t = tid - 128;
        const float4 z = make_float4(0.f, 0.f, 0.f, 0.f);
        #pragma unroll
        for (int g = 0; g < 2; g++) {
            const int c  = t + g * 128;       // float4-column 0..255
            const int dd = (c >> 1) - i;      // block-col offset from i
            if (dd == 0 || dd < -2 || dd > 2) {   // not a live band column
                float* col = out + base + (size_t)c * 4;
                #pragma unroll 2
                for (int rc = 0; rc < 8; rc++) {
                    float* pr = col + (size_t)rc * (1024 * 1024);
                    #pragma unroll
                    for (int rh = 0; rh < 8; rh++)
                        stcs4(pr + rh * 1024, z);
                }
            }
        }
        return;
    }

    // ================= CONV WARPS (tid 0..127) =================
    // thread = (slab, co-pair): slab = tid>>2 (32 slabs), co2 = (tid&3)*2
    const int slab = tid >> 2;
    const int co2  = (tid & 3) << 1;
    const int pp   = slab >> 3;
    const int hh   = slab & 7;
    const int doff = (pp < 2) ? (pp - 2) : (pp - 1);  // {-2,-1,1,2}
    const int j    = i + doff;
    const bool pvalid = (j >= 0) && (j < 128);

    // conv params -> SMEM
    for (int t = tid; t < NLAYERS * 64; t += 128) {
        const int l = t >> 6, rem = t & 63, wco = rem >> 3, wci = rem & 7;
        const float* src = conv_w + ((l * 8 + wco) * 8 + wci) * 3;
        sW4[l][wci][wco] = make_float4(src[0], src[1], src[2], 0.f);
    }
    if (tid < NLAYERS * 8) (&sB[0][0])[tid] = conv_b[tid];
    if (tid < NLAYERS)     sA[tid] = prelu_a[tid];

    // load x for both channels (8 contiguous floats each)
    float4 a0 = make_float4(0.f,0.f,0.f,0.f), a1 = a0, b0 = a0, b1 = a0;
    if (pvalid) {
        const float* srcA = pw +
            ((size_t)((b * 8 + co2) * 1024 + (i * 8 + hh)) * 1024 + (size_t)j * 8);
        const float* srcB = srcA + (size_t)1024 * 1024;   // co2+1
        a0 = *(const float4*)srcA; a1 = *(const float4*)(srcA + 4);
        b0 = *(const float4*)srcB; b1 = *(const float4*)(srcB + 4);
    }
    {
        float* rowA = sD0 + slab * 68 + co2 * 8;
        *(float4*)rowA        = a0;  *(float4*)(rowA + 4)  = a1;
        *(float4*)(rowA + 8)  = b0;  *(float4*)(rowA + 12) = b1;
        *(float4*)&sRes[pp][hh][co2][0]     = a0;
        *(float4*)&sRes[pp][hh][co2][4]     = a1;
        *(float4*)&sRes[pp][hh][co2 + 1][0] = b0;
        *(float4*)&sRes[pp][hh][co2 + 1][4] = b1;
    }
    convbar();

    // ---- 7-layer residual conv stack ----
    float* cur = sD0;
    float* nxt = sD1;
    #pragma unroll 1
    for (int l = 0; l < NLAYERS; l++) {
        float accA[8], accB[8];
        const float biasA = sB[l][co2];
        const float biasB = sB[l][co2 + 1];
        #pragma unroll
        for (int w = 0; w < 8; w++) { accA[w] = biasA; accB[w] = biasB; }

        #pragma unroll
        for (int ci = 0; ci < 8; ci++) {
            const float4 wa = sW4[l][ci][co2];
            const float4 wb = sW4[l][ci][co2 + 1];
            const float* inr = cur + slab * 68 + ci * 8;
            const float4 ra = *(const float4*)inr;
            const float4 rb = *(const float4*)(inr + 4);
            accA[0] += wa.y * ra.x + wa.z * ra.y;
            accA[1] += wa.x * ra.x + wa.y * ra.y + wa.z * ra.z;
            accA[2] += wa.x * ra.y + wa.y * ra.z + wa.z * ra.w;
            accA[3] += wa.x * ra.z + wa.y * ra.w + wa.z * rb.x;
            accA[4] += wa.x * ra.w + wa.y * rb.x + wa.z * rb.y;
            accA[5] += wa.x * rb.x + wa.y * rb.y + wa.z * rb.z;
            accA[6] += wa.x * rb.y + wa.y * rb.z + wa.z * rb.w;
            accA[7] += wa.x * rb.z + wa.y * rb.w;
            accB[0] += wb.y * ra.x + wb.z * ra.y;
            accB[1] += wb.x * ra.x + wb.y * ra.y + wb.z * ra.z;
            accB[2] += wb.x * ra.y + wb.y * ra.z + wb.z * ra.w;
            accB[3] += wb.x * ra.z + wb.y * ra.w + wb.z * rb.x;
            accB[4] += wb.x * ra.w + wb.y * rb.x + wb.z * rb.y;
            accB[5] += wb.x * rb.x + wb.y * rb.y + wb.z * rb.z;
            accB[6] += wb.x * rb.y + wb.y * rb.z + wb.z * rb.w;
            accB[7] += wb.x * rb.z + wb.y * rb.w;
        }

        const float pa = sA[l];
        const float* selfA = cur + slab * 68 + co2 * 8;
        const float4 sa0 = *(const float4*)selfA;
        const float4 sa1 = *(const float4*)(selfA + 4);
        const float4 sb0 = *(const float4*)(selfA + 8);
        const float4 sb1 = *(const float4*)(selfA + 12);
        float4 oA0, oA1, oB0, oB1;
        oA0.x = ((accA[0]>=0.f)?accA[0]:pa*accA[0]) + sa0.x;
        oA0.y = ((accA[1]>=0.f)?accA[1]:pa*accA[1]) + sa0.y;
        oA0.z = ((accA[2]>=0.f)?accA[2]:pa*accA[2]) + sa0.z;
        oA0.w = ((accA[3]>=0.f)?accA[3]:pa*accA[3]) + sa0.w;
        oA1.x = ((accA[4]>=0.f)?accA[4]:pa*accA[4]) + sa1.x;
        oA1.y = ((accA[5]>=0.f)?accA[5]:pa*accA[5]) + sa1.y;
        oA1.z = ((accA[6]>=0.f)?accA[6]:pa*accA[6]) + sa1.z;
        oA1.w = ((accA[7]>=0.f)?accA[7]:pa*accA[7]) + sa1.w;
        oB0.x = ((accB[0]>=0.f)?accB[0]:pa*accB[0]) + sb0.x;
        oB0.y = ((accB[1]>=0.f)?accB[1]:pa*accB[1]) + sb0.y;
        oB0.z = ((accB[2]>=0.f)?accB[2]:pa*accB[2]) + sb0.z;
        oB0.w = ((accB[3]>=0.f)?accB[3]:pa*accB[3]) + sb0.w;
        oB1.x = ((accB[4]>=0.f)?accB[4]:pa*accB[4]) + sb1.x;
        oB1.y = ((accB[5]>=0.f)?accB[5]:pa*accB[5]) + sb1.y;
        oB1.z = ((accB[6]>=0.f)?accB[6]:pa*accB[6]) + sb1.z;
        oB1.w = ((accB[7]>=0.f)?accB[7]:pa*accB[7]) + sb1.w;
        float* outr = nxt + slab * 68 + co2 * 8;
        *(float4*)outr        = oA0;  *(float4*)(outr + 4)  = oA1;
        *(float4*)(outr + 8)  = oB0;  *(float4*)(outr + 12) = oB1;
        convbar();
        float* tmp = cur; cur = nxt; nxt = tmp;
    }

    // ---- we = expm1(relu(x - sigmoid(conv)) * (1-eye)) for both channels ----
    #pragma unroll
    for (int cc = 0; cc < 2; cc++) {
        const int co = co2 + cc;
        const float* cr = cur + slab * 68 + co * 8;
        const float4 c0 = *(const float4*)cr;
        const float4 c1 = *(const float4*)(cr + 4);
        const float4 x0 = *(const float4*)&sRes[pp][hh][co][0];
        const float4 x1 = *(const float4*)&sRes[pp][hh][co][4];
        float cv[8] = {c0.x,c0.y,c0.z,c0.w,c1.x,c1.y,c1.z,c1.w};
        float xv[8] = {x0.x,x0.y,x0.z,x0.w,x1.x,x1.y,x1.z,x1.w};
        float we[8];
        float partial = 0.f;
        #pragma unroll
        for (int w = 0; w < 8; w++) {
            const float sg = 1.f / (1.f + __expf(-cv[w]));
            float sp = fmaxf(xv[w] - sg, 0.f);
            if (hh == w) sp = 0.f;
            float v = expm1f(sp);
            if (!pvalid) v = 0.f;
            we[w] = v;
            partial += v;
        }
        *(float4*)&sRes[pp][hh][co][0] = make_float4(we[0],we[1],we[2],we[3]);
        *(float4*)&sRes[pp][hh][co][4] = make_float4(we[4],we[5],we[6],we[7]);
        sPS[pp][hh][co] = partial;
    }
    convbar();

    if (tid < 64) {
        const int th = tid >> 3, tc = tid & 7;
        const float s = sPS[0][th][tc] + sPS[1][th][tc] + sPS[2][th][tc] + sPS[3][th][tc];
        sInv[th][tc] = 1.f / (s + EPS_F);
    }
    convbar();

    // ---- band stores: 8 float4-columns x 64 rows over 128 threads ----
    {
        const int cI   = tid >> 4;          // 0..7 band column slot
        const int r0   = tid & 15;          // row group start
        const int dIdx = cI >> 1;           // pp index
        const int half = cI & 1;
        const int dv   = (dIdx < 2) ? (dIdx - 2) : (dIdx - 1);
        const int jb   = i + dv;
        if (jb >= 0 && jb < 128) {
            const int fc = 2 * jb + half;
            const int w0 = half * 4;
            #pragma unroll
            for (int g = 0; g < 4; g++) {
                const int rr = r0 + g * 16;     // 0..63
                const int rc = rr >> 3, rh = rr & 7;
                const float4 rv = *(const float4*)&sRes[dIdx][rh][rc][w0];
                const float inv = sInv[rh][rc];
                stcs4(out + base + (size_t)rc * (1024*1024) + rh * 1024 + fc * 4,
                      make_float4(rv.x*inv, rv.y*inv, rv.z*inv, rv.w*inv));
            }
        }
    }
}

extern "C" void kernel_launch(void* const* d_in, const int* in_sizes, int n_in,
                              void* d_out, int out_size) {
    const float* pw = (const float*)d_in[0];
    const float* cw = (const float*)d_in[1];
    const float* cb = (const float*)d_in[2];
    const float* pa = (const float*)d_in[3];
    sag_ws<<<1024, 256>>>(pw, cw, cb, pa, (float*)d_out);
}

// round 9
// speedup vs baseline: 1.3550x; 1.3455x over previous
#include <cuda_runtime.h>

#define NLAYERS 7
#define EPS_F 1e-5f

// Shapes (fixed by setup_inputs): bsz=8, C=8, QL=KL=128, A=8, cross_range=2
// pw / out: [64, 1024, 1024] f32;  conv_w: [7,8,8,1,3]; conv_b: [7,8]; prelu_a: [7]
//
// One CTA per (b, q). Register-resident conv: the 8 channels of one slab live
// in 8 consecutive lanes of a warp, so channel mixing is done with
// __shfl_sync (no SMEM ping-pong, no per-layer barriers). Zero stores for the
// 248 dead float4-columns are interleaved one slice per conv layer so DRAM is
// fed continuously. Band values are stored straight from registers.

__device__ __forceinline__ void stcs4(float* p, float4 v) {
    asm volatile("st.global.cs.v4.f32 [%0], {%1,%2,%3,%4};"
                 :: "l"(p), "f"(v.x), "f"(v.y), "f"(v.z), "f"(v.w) : "memory");
}

__global__ __launch_bounds__(256, 4)
void sag_shfl(const float* __restrict__ pw,
              const float* __restrict__ conv_w,
              const float* __restrict__ conv_b,
              const float* __restrict__ prelu_a,
              float* __restrict__ out)
{
    __shared__ float4 sW4[NLAYERS][8][8];   // [l][ci][co] = (k0,k1,k2,_)
    __shared__ float  sB [NLAYERS][8];
    __shared__ float  sA [NLAYERS];
    __shared__ float  sPS[4][8][8];         // partial row sums [pp][hh][co]
    __shared__ float  sInv[8][8];           // 1/(rowsum+eps)   [hh][co]

    const int tid = threadIdx.x;
    const int b = blockIdx.x >> 7;          // batch
    const int i = blockIdx.x & 127;         // query index
    const size_t base = ((size_t)(b * 8) * 1024 + (size_t)i * 8) * 1024;

    // compute roles: slab = pp*8+hh in lanes-of-8, co = lane&7
    const int slab = tid >> 3;
    const int co   = tid & 7;
    const int pp   = slab >> 3;
    const int hh   = slab & 7;
    const int doff = (pp < 2) ? (pp - 2) : (pp - 1);  // {-2,-1,1,2}
    const int j    = i + doff;
    const bool pvalid = (j >= 0) && (j < 128);

    // ---- x load (issued first) ----
    float4 v0 = make_float4(0.f,0.f,0.f,0.f), v1 = v0;
    const float* srcx = pw +
        ((size_t)((b * 8 + co) * 1024 + (i * 8 + hh)) * 1024 + (size_t)(pvalid ? j : 0) * 8);
    if (pvalid) { v0 = *(const float4*)srcx; v1 = *(const float4*)(srcx + 4); }

    // store roles: float4-column = tid; zero columns are d==0 or |d|>2
    const int d = (tid >> 1) - i;
    const bool zcol = (d == 0) || (d < -2) || (d > 2);
    float* colbase = out + base + (size_t)tid * 4;
    const float4 z = make_float4(0.f, 0.f, 0.f, 0.f);

    // ---- zero slice 0 (channel row 0) ----
    if (zcol) {
        #pragma unroll
        for (int rh = 0; rh < 8; rh++) stcs4(colbase + rh * 1024, z);
    }

    // ---- conv params -> SMEM ----
    for (int t = tid; t < NLAYERS * 64; t += 256) {
        const int l = t >> 6, rem = t & 63, wco = rem >> 3, wci = rem & 7;
        const float* s = conv_w + ((l * 8 + wco) * 8 + wci) * 3;
        sW4[l][wci][wco] = make_float4(s[0], s[1], s[2], 0.f);
    }
    if (tid < NLAYERS * 8) (&sB[0][0])[tid] = conv_b[tid];
    if (tid < NLAYERS)     sA[tid] = prelu_a[tid];
    __syncthreads();

    float x[8] = {v0.x, v0.y, v0.z, v0.w, v1.x, v1.y, v1.z, v1.w};
    float c[8];
    #pragma unroll
    for (int w = 0; w < 8; w++) c[w] = x[w];

    const int lane  = tid & 31;
    const int gbase = lane & 24;            // slab group base lane

    // ---- 7-layer residual conv stack, register-resident via shuffles ----
    #pragma unroll 1
    for (int l = 0; l < NLAYERS; l++) {
        const float bias = sB[l][co];
        float acc[8];
        #pragma unroll
        for (int w = 0; w < 8; w++) acc[w] = bias;

        #pragma unroll
        for (int ci = 0; ci < 8; ci++) {
            const float4 wv = sW4[l][ci][co];
            const int src = gbase | ci;
            const float r0 = __shfl_sync(0xffffffffu, c[0], src);
            const float r1 = __shfl_sync(0xffffffffu, c[1], src);
            const float r2 = __shfl_sync(0xffffffffu, c[2], src);
            const float r3 = __shfl_sync(0xffffffffu, c[3], src);
            const float r4 = __shfl_sync(0xffffffffu, c[4], src);
            const float r5 = __shfl_sync(0xffffffffu, c[5], src);
            const float r6 = __shfl_sync(0xffffffffu, c[6], src);
            const float r7 = __shfl_sync(0xffffffffu, c[7], src);
            acc[0] += wv.y * r0 + wv.z * r1;
            acc[1] += wv.x * r0 + wv.y * r1 + wv.z * r2;
            acc[2] += wv.x * r1 + wv.y * r2 + wv.z * r3;
            acc[3] += wv.x * r2 + wv.y * r3 + wv.z * r4;
            acc[4] += wv.x * r3 + wv.y * r4 + wv.z * r5;
            acc[5] += wv.x * r4 + wv.y * r5 + wv.z * r6;
            acc[6] += wv.x * r5 + wv.y * r6 + wv.z * r7;
            acc[7] += wv.x * r6 + wv.y * r7;
        }

        // interleaved zero slice (channel row l+1) — independent of conv data
        if (zcol) {
            float* pr = colbase + (size_t)(l + 1) * (1024 * 1024);
            #pragma unroll
            for (int rh = 0; rh < 8; rh++) stcs4(pr + rh * 1024, z);
        }

        const float pa = sA[l];
        #pragma unroll
        for (int w = 0; w < 8; w++) {
            const float y = (acc[w] >= 0.f) ? acc[w] : pa * acc[w];
            c[w] = y + c[w];                // residual, in place
        }
    }

    // ---- we = expm1(relu(x - sigmoid(conv)) * (1-eye)) ----
    float we[8];
    float partial = 0.f;
    #pragma unroll
    for (int w = 0; w < 8; w++) {
        const float sg = 1.f / (1.f + __expf(-c[w]));
        float sp = fmaxf(x[w] - sg, 0.f);
        if (hh == w) sp = 0.f;              // self mask
        float v = expm1f(sp);
        if (!pvalid) v = 0.f;
        we[w] = v;
        partial += v;
    }
    sPS[pp][hh][co] = partial;
    __syncthreads();

    if (tid < 64) {
        const int th = tid >> 3, tc = tid & 7;
        const float s = sPS[0][th][tc] + sPS[1][th][tc] + sPS[2][th][tc] + sPS[3][th][tc];
        sInv[th][tc] = 1.f / (s + EPS_F);
    }
    __syncthreads();

    // ---- band store straight from registers (disjoint from zcol columns) ----
    if (pvalid) {
        const float inv = sInv[hh][co];
        float* dst = out +
            ((size_t)((b * 8 + co) * 1024 + (i * 8 + hh)) * 1024 + (size_t)j * 8);
        stcs4(dst,     make_float4(we[0]*inv, we[1]*inv, we[2]*inv, we[3]*inv));
        stcs4(dst + 4, make_float4(we[4]*inv, we[5]*inv, we[6]*inv, we[7]*inv));
    }
}

extern "C" void kernel_launch(void* const* d_in, const int* in_sizes, int n_in,
                              void* d_out, int out_size) {
    const float* pw = (const float*)d_in[0];
    const float* cw = (const float*)d_in[1];
    const float* cb = (const float*)d_in[2];
    const float* pa = (const float*)d_in[3];
    sag_shfl<<<1024, 256>>>(pw, cw, cb, pa, (float*)d_out);
}